// round 1
// baseline (speedup 1.0000x reference)
#include <cuda_runtime.h>
#include <math.h>

// Problem constants
constexpr int B = 2, L = 2048, D = 1024, H = 16, DK = 64;
constexpr int M = B * L;                         // 4096 rows
constexpr int OUT_ELEMS = B * L * D;             // 4,194,304
constexpr long long ATTN_ELEMS = (long long)B * H * L * L;  // 134,217,728

// Device scratch (static — no runtime allocation allowed)
__device__ float g_Q[B * H * L * DK];   // (b,h,l,dk)
__device__ float g_K[B * H * L * DK];
__device__ float g_V[B * H * L * DK];
__device__ float g_O[B * L * H * DK];   // (b,l, h*dv) — row-major for FC
__device__ float g_X[B * L * D];        // FC output + residual, pre-LN
__device__ float g_rsum[B * H * L];     // softmax row sums

// ---------------------------------------------------------------------------
// 128x128x8 SGEMM, 256 threads, 8x8 per thread.
// MODE 0/1/2: C = A @ W, scatter-store to g_Q/g_K/g_V in (b,h,l,dk) layout.
// MODE 3:     C = g_O @ W + resid, store to g_X.
// ---------------------------------------------------------------------------
template <int MODE>
__global__ void __launch_bounds__(256) gemm128(const float* __restrict__ Ain,
                                               const float* __restrict__ W,
                                               const float* __restrict__ resid) {
  __shared__ float As[8][132];
  __shared__ float Ws[8][132];
  const float* A = (MODE == 3) ? (const float*)g_O : Ain;

  const int tid = threadIdx.x;
  const int tx = tid & 15, ty = tid >> 4;
  const int m0 = blockIdx.y * 128, n0 = blockIdx.x * 128;
  const int a_r = tid >> 1;            // 0..127
  const int a_c = (tid & 1) * 4;       // 0 or 4
  const int w_r = tid >> 5;            // 0..7
  const int w_c = (tid & 31) * 4;      // 0..124

  float acc[8][8];
#pragma unroll
  for (int i = 0; i < 8; i++)
#pragma unroll
    for (int j = 0; j < 8; j++) acc[i][j] = 0.f;

  for (int kt = 0; kt < D; kt += 8) {
    float4 av = *(const float4*)&A[(size_t)(m0 + a_r) * D + kt + a_c];
    float4 wv = *(const float4*)&W[(size_t)(kt + w_r) * D + n0 + w_c];
    As[a_c + 0][a_r] = av.x;
    As[a_c + 1][a_r] = av.y;
    As[a_c + 2][a_r] = av.z;
    As[a_c + 3][a_r] = av.w;
    *(float4*)&Ws[w_r][w_c] = wv;
    __syncthreads();
#pragma unroll
    for (int kk = 0; kk < 8; kk++) {
      float a[8], b[8];
      *(float4*)&a[0] = *(const float4*)&As[kk][ty * 8];
      *(float4*)&a[4] = *(const float4*)&As[kk][ty * 8 + 4];
      *(float4*)&b[0] = *(const float4*)&Ws[kk][tx * 8];
      *(float4*)&b[4] = *(const float4*)&Ws[kk][tx * 8 + 4];
#pragma unroll
      for (int i = 0; i < 8; i++)
#pragma unroll
        for (int j = 0; j < 8; j++) acc[i][j] = fmaf(a[i], b[j], acc[i][j]);
    }
    __syncthreads();
  }

  if (MODE <= 2) {
    float* dst = (MODE == 0) ? g_Q : (MODE == 1) ? g_K : g_V;
#pragma unroll
    for (int i = 0; i < 8; i++) {
      int m = m0 + ty * 8 + i;
      int bb = m >> 11;            // m / L
      int l = m & (L - 1);
      int n = n0 + tx * 8;
      int hh = n >> 6;             // stays constant across the 8 j's (8-aligned)
      int dk = n & 63;
      float* p = &dst[(((size_t)(bb * H + hh) * L) + l) * DK + dk];
      *(float4*)p = make_float4(acc[i][0], acc[i][1], acc[i][2], acc[i][3]);
      *(float4*)(p + 4) = make_float4(acc[i][4], acc[i][5], acc[i][6], acc[i][7]);
    }
  } else {
#pragma unroll
    for (int i = 0; i < 8; i++) {
      int m = m0 + ty * 8 + i;
      int n = n0 + tx * 8;
      float4 r0 = *(const float4*)&resid[(size_t)m * D + n];
      float4 r1 = *(const float4*)&resid[(size_t)m * D + n + 4];
      *(float4*)&g_X[(size_t)m * D + n] = make_float4(
          acc[i][0] + r0.x, acc[i][1] + r0.y, acc[i][2] + r0.z, acc[i][3] + r0.w);
      *(float4*)&g_X[(size_t)m * D + n + 4] = make_float4(
          acc[i][4] + r1.x, acc[i][5] + r1.y, acc[i][6] + r1.z, acc[i][7] + r1.w);
    }
  }
}

// ---------------------------------------------------------------------------
// Fused attention: per (b, h, 128-row q-tile), loop over 64-wide k-tiles.
// Computes E = exp(QK^T/8) with mask, writes unnormalized E to attn output,
// accumulates row sums and O = E @ V, then stores O / rowsum.
// ---------------------------------------------------------------------------
__global__ void __launch_bounds__(256) attn_kernel(const int* __restrict__ mask,
                                                   float* __restrict__ attnE) {
  extern __shared__ float sm[];
  float* QsT = sm;                  // [64][132], d-major: QsT[d][r]
  float* KsT = sm + 64 * 132;       // [64][68],  d-major: KsT[d][c]
  float* Vs = KsT + 64 * 68;        // [64][68],  Vs[c][dv]
  float* EsT = Vs + 64 * 68;        // [64][132], k-major: EsT[kk][r]
  __shared__ float rsum_s[128];

  const int tid = threadIdx.x;
  const int tx = tid & 15, ty = tid >> 4;
  const int b = blockIdx.z, h = blockIdx.y;
  const int q0 = blockIdx.x * 128;
  const int bh = b * H + h;
  const float* Qb = g_Q + ((size_t)bh * L + q0) * DK;
  const float* Kb = g_K + (size_t)bh * L * DK;
  const float* Vb = g_V + (size_t)bh * L * DK;

  // Load Q tile (128x64) transposed
#pragma unroll
  for (int it = 0; it < 8; it++) {
    int o = (tid + it * 256) * 4;   // 0..8188
    int r = o >> 6, d = o & 63;
    float4 v4 = *(const float4*)&Qb[o];
    QsT[(d + 0) * 132 + r] = v4.x;
    QsT[(d + 1) * 132 + r] = v4.y;
    QsT[(d + 2) * 132 + r] = v4.z;
    QsT[(d + 3) * 132 + r] = v4.w;
  }

  float rs[8];
  float acc_o[8][4];
#pragma unroll
  for (int i = 0; i < 8; i++) {
    rs[i] = 0.f;
#pragma unroll
    for (int j = 0; j < 4; j++) acc_o[i][j] = 0.f;
  }

  for (int k0 = 0; k0 < L; k0 += 64) {
    __syncthreads();  // previous EV readers done before overwriting tiles
    // Load K (transposed) and V tiles (64x64 each)
#pragma unroll
    for (int it = 0; it < 4; it++) {
      int o = (tid + it * 256) * 4;  // 0..4092
      int c = o >> 6, d = o & 63;
      float4 kv = *(const float4*)&Kb[(size_t)(k0 + c) * DK + d];
      KsT[(d + 0) * 68 + c] = kv.x;
      KsT[(d + 1) * 68 + c] = kv.y;
      KsT[(d + 2) * 68 + c] = kv.z;
      KsT[(d + 3) * 68 + c] = kv.w;
      float4 vv = *(const float4*)&Vb[(size_t)(k0 + c) * DK + d];
      *(float4*)&Vs[c * 68 + d] = vv;
    }
    __syncthreads();

    // S tile: 128x64, 8x4 per thread
    float acc_s[8][4];
#pragma unroll
    for (int i = 0; i < 8; i++)
#pragma unroll
      for (int j = 0; j < 4; j++) acc_s[i][j] = 0.f;

#pragma unroll 8
    for (int d = 0; d < 64; d++) {
      float a[8], bb4[4];
      *(float4*)&a[0] = *(const float4*)&QsT[d * 132 + ty * 8];
      *(float4*)&a[4] = *(const float4*)&QsT[d * 132 + ty * 8 + 4];
      *(float4*)&bb4[0] = *(const float4*)&KsT[d * 68 + tx * 4];
#pragma unroll
      for (int i = 0; i < 8; i++)
#pragma unroll
        for (int j = 0; j < 4; j++) acc_s[i][j] = fmaf(a[i], bb4[j], acc_s[i][j]);
    }

    // Epilogue: mask, exp, write E (smem transposed + optional gmem), rowsum
#pragma unroll
    for (int i = 0; i < 8; i++) {
      int qr = q0 + ty * 8 + i;
      int4 mv = *(const int4*)&mask[((size_t)b * L + qr) * L + k0 + tx * 4];
      int mm[4] = {mv.x, mv.y, mv.z, mv.w};
      float e[4];
#pragma unroll
      for (int j = 0; j < 4; j++) {
        float s = acc_s[i][j] * 0.125f;
        float ev = (mm[j] != 0) ? __expf(fminf(s, 60.f)) : 0.f;
        e[j] = ev;
        rs[i] += ev;
        EsT[(tx * 4 + j) * 132 + ty * 8 + i] = ev;
      }
      if (attnE) {
        *(float4*)&attnE[((size_t)bh * L + qr) * L + k0 + tx * 4] =
            make_float4(e[0], e[1], e[2], e[3]);
      }
    }
    __syncthreads();

    // O += E @ V
#pragma unroll 8
    for (int kk = 0; kk < 64; kk++) {
      float a[8], bb4[4];
      *(float4*)&a[0] = *(const float4*)&EsT[kk * 132 + ty * 8];
      *(float4*)&a[4] = *(const float4*)&EsT[kk * 132 + ty * 8 + 4];
      *(float4*)&bb4[0] = *(const float4*)&Vs[kk * 68 + tx * 4];
#pragma unroll
      for (int i = 0; i < 8; i++)
#pragma unroll
        for (int j = 0; j < 4; j++) acc_o[i][j] = fmaf(a[i], bb4[j], acc_o[i][j]);
    }
  }

  // Reduce row sums across the 16 tx lanes (lanes 0..15 / 16..31 are separate rows)
#pragma unroll
  for (int i = 0; i < 8; i++) {
    float v = rs[i];
    v += __shfl_xor_sync(0xffffffffu, v, 8);
    v += __shfl_xor_sync(0xffffffffu, v, 4);
    v += __shfl_xor_sync(0xffffffffu, v, 2);
    v += __shfl_xor_sync(0xffffffffu, v, 1);
    if (tx == 0) rsum_s[ty * 8 + i] = v;
  }
  __syncthreads();
  if (tid < 128) g_rsum[(size_t)bh * L + q0 + tid] = rsum_s[tid];

  // Store normalized O in (b, l, h*dv) layout
#pragma unroll
  for (int i = 0; i < 8; i++) {
    float inv = 1.f / rsum_s[ty * 8 + i];
    int qr = q0 + ty * 8 + i;
    *(float4*)&g_O[((size_t)b * L + qr) * (H * DK) + h * DK + tx * 4] =
        make_float4(acc_o[i][0] * inv, acc_o[i][1] * inv,
                    acc_o[i][2] * inv, acc_o[i][3] * inv);
  }
}

// Normalize attn rows by 1/rowsum (one block per (bh, row))
__global__ void __launch_bounds__(256) attn_norm(float* __restrict__ attnE) {
  const int row = blockIdx.x;
  const int bh = blockIdx.y;
  const float inv = 1.f / g_rsum[(size_t)bh * L + row];
  float* p = attnE + ((size_t)bh * L + row) * L;
#pragma unroll
  for (int it = 0; it < 2; it++) {
    int o = (threadIdx.x + it * 256) * 4;
    float4 v = *(const float4*)&p[o];
    v.x *= inv; v.y *= inv; v.z *= inv; v.w *= inv;
    *(float4*)&p[o] = v;
  }
}

// LayerNorm over last dim (one block per row)
__global__ void __launch_bounds__(256) ln_kernel(const float* __restrict__ gamma,
                                                 const float* __restrict__ beta,
                                                 float* __restrict__ out) {
  const int row = blockIdx.x;
  const int tid = threadIdx.x;
  const float* x = g_X + (size_t)row * D;
  float4 v = *(const float4*)&x[tid * 4];
  float s = v.x + v.y + v.z + v.w;
  float s2 = v.x * v.x + v.y * v.y + v.z * v.z + v.w * v.w;
#pragma unroll
  for (int off = 16; off; off >>= 1) {
    s += __shfl_xor_sync(0xffffffffu, s, off);
    s2 += __shfl_xor_sync(0xffffffffu, s2, off);
  }
  __shared__ float ws[8], ws2[8];
  __shared__ float mean_s, rstd_s;
  int wid = tid >> 5, lid = tid & 31;
  if (lid == 0) { ws[wid] = s; ws2[wid] = s2; }
  __syncthreads();
  if (tid == 0) {
    float S = 0.f, S2 = 0.f;
#pragma unroll
    for (int w = 0; w < 8; w++) { S += ws[w]; S2 += ws2[w]; }
    float mu = S * (1.f / D);
    float var = S2 * (1.f / D) - mu * mu;
    mean_s = mu;
    rstd_s = rsqrtf(var + 1e-6f);
  }
  __syncthreads();
  float mu = mean_s, rstd = rstd_s;
  float4 g4 = *(const float4*)&gamma[tid * 4];
  float4 b4 = *(const float4*)&beta[tid * 4];
  float4 o;
  o.x = (v.x - mu) * rstd * g4.x + b4.x;
  o.y = (v.y - mu) * rstd * g4.y + b4.y;
  o.z = (v.z - mu) * rstd * g4.z + b4.z;
  o.w = (v.w - mu) * rstd * g4.w + b4.w;
  *(float4*)&out[(size_t)row * D + tid * 4] = o;
}

extern "C" void kernel_launch(void* const* d_in, const int* in_sizes, int n_in,
                              void* d_out, int out_size) {
  const float* q = (const float*)d_in[0];
  const float* k = (const float*)d_in[1];
  const float* v = (const float*)d_in[2];
  const int* mask = (const int*)d_in[3];
  const float* wq = (const float*)d_in[4];
  const float* wk = (const float*)d_in[5];
  const float* wv = (const float*)d_in[6];
  const float* wfc = (const float*)d_in[7];
  const float* lng = (const float*)d_in[8];
  const float* lnb = (const float*)d_in[9];
  (void)in_sizes; (void)n_in;

  float* out = (float*)d_out;
  float* attn = nullptr;
  if ((long long)out_size >= (long long)OUT_ELEMS + ATTN_ELEMS)
    attn = out + OUT_ELEMS;

  dim3 gemm_grid(D / 128, M / 128);
  gemm128<0><<<gemm_grid, 256>>>(q, wq, nullptr);
  gemm128<1><<<gemm_grid, 256>>>(k, wk, nullptr);
  gemm128<2><<<gemm_grid, 256>>>(v, wv, nullptr);

  cudaFuncSetAttribute(attn_kernel, cudaFuncAttributeMaxDynamicSharedMemorySize,
                       102400);
  attn_kernel<<<dim3(L / 128, H, B), 256, 102400>>>(mask, attn);
  if (attn) attn_norm<<<dim3(L, B * H), 256>>>(attn);

  gemm128<3><<<gemm_grid, 256>>>(nullptr, wfc, q);
  ln_kernel<<<M, 256>>>(lng, lnb, out);
}